// round 7
// baseline (speedup 1.0000x reference)
#include <cuda_runtime.h>
#include <cuda_fp16.h>

#define FD 128
#define NMAX 51200   // headroom over N=50000

// Scratch: Wh = (W + W^T) fp16, G = feats @ Ws (fp16), feats copy (fp16).
__device__ __half g_Wh[FD * FD];
__device__ __half g_Gh[(size_t)NMAX * FD];
__device__ __half g_Fh[(size_t)NMAX * FD];

// ---------------------------------------------------------------------------
// Kernel 1: build Wh = fp16(W + W^T) and zero the (poisoned) output.
// ---------------------------------------------------------------------------
__global__ void prep_kernel(const float* __restrict__ W,
                            float* __restrict__ out, int M) {
    int t = blockIdx.x * blockDim.x + threadIdx.x;
    if (t < FD * FD) {
        int r = t >> 7;
        int c = t & 127;
        g_Wh[t] = __float2half_rn(W[t] + W[c * FD + r]);
    }
    if (t < M) out[t] = 0.0f;
}

// ---------------------------------------------------------------------------
// XOR swizzle on 16-byte chunks.
// ---------------------------------------------------------------------------
__device__ __forceinline__ int swz_off(int row, int col_halves) {
    int chunk = col_halves >> 3;
    int within = col_halves & 7;
    return row * FD + ((chunk ^ (row & 7)) << 3) + within;
}

// ---------------------------------------------------------------------------
// Kernel 2: G = feats @ Ws via HMMA (m16n8k16 fp16 in / fp32 acc).
// Unchanged from R6 (measured-good).
// ---------------------------------------------------------------------------
__global__ __launch_bounds__(256) void gemm_mma_kernel(const float* __restrict__ feats,
                                                       int N) {
    __shared__ __half sA[64 * FD];
    __shared__ __half sB[128 * FD];

    const int base = blockIdx.x * 64;
    const int tid = threadIdx.x;

    int nval = N - base;
    if (nval > 64) nval = 64;

    {
        const uint2* src = (const uint2*)g_Wh;
        for (int i = tid; i < 128 * 32; i += 256) {
            int row = i >> 5, c4 = i & 31;
            *(uint2*)&sB[swz_off(row, c4 * 4)] = src[i];
        }
    }
    {
        const float4* src = (const float4*)feats + (size_t)base * 32;
        uint2* fh_dst = (uint2*)(g_Fh + (size_t)base * FD);
        for (int i = tid; i < 64 * 32; i += 256) {
            int row = i >> 5, c4 = i & 31;
            uint2 p = make_uint2(0u, 0u);
            if (row < nval) {
                float4 v = src[i];
                __half2 h0 = __floats2half2_rn(v.x, v.y);
                __half2 h1 = __floats2half2_rn(v.z, v.w);
                p.x = *(unsigned int*)&h0;
                p.y = *(unsigned int*)&h1;
                fh_dst[i] = p;
            }
            *(uint2*)&sA[swz_off(row, c4 * 4)] = p;
        }
    }
    __syncthreads();

    const int warp = tid >> 5;
    const int lane = tid & 31;
    const int mr = warp >> 1;
    const int nc = warp & 1;

    float acc[8][4];
#pragma unroll
    for (int b = 0; b < 8; b++)
#pragma unroll
        for (int q = 0; q < 4; q++) acc[b][q] = 0.0f;

    const int arow = mr * 16 + (lane & 15);
    const int a_kchunk_base = (lane >> 4);
    const int krow_lane = (lane & 7) + ((lane >> 3) & 1) * 8;
    const int b_nadd = (lane >> 4) * 8;

#pragma unroll
    for (int kk = 0; kk < 8; kk++) {
        unsigned a0, a1, a2, a3;
        {
            int koff = kk * 16 + a_kchunk_base * 8;
            unsigned addr = (unsigned)__cvta_generic_to_shared(&sA[swz_off(arow, koff)]);
            asm volatile("ldmatrix.sync.aligned.m8n8.x4.shared.b16 {%0,%1,%2,%3}, [%4];"
                         : "=r"(a0), "=r"(a1), "=r"(a2), "=r"(a3) : "r"(addr));
        }
        const int krow = kk * 16 + krow_lane;
#pragma unroll
        for (int nb2 = 0; nb2 < 4; nb2++) {
            unsigned b0, b1, b2, b3;
            int ncol = nc * 64 + nb2 * 16 + b_nadd;
            unsigned addr = (unsigned)__cvta_generic_to_shared(&sB[swz_off(krow, ncol)]);
            asm volatile("ldmatrix.sync.aligned.m8n8.x4.trans.shared.b16 {%0,%1,%2,%3}, [%4];"
                         : "=r"(b0), "=r"(b1), "=r"(b2), "=r"(b3) : "r"(addr));
            float* c0 = acc[2 * nb2];
            asm volatile("mma.sync.aligned.m16n8k16.row.col.f32.f16.f16.f32 "
                         "{%0,%1,%2,%3}, {%4,%5,%6,%7}, {%8,%9}, {%0,%1,%2,%3};"
                         : "+f"(c0[0]), "+f"(c0[1]), "+f"(c0[2]), "+f"(c0[3])
                         : "r"(a0), "r"(a1), "r"(a2), "r"(a3), "r"(b0), "r"(b1));
            float* c1 = acc[2 * nb2 + 1];
            asm volatile("mma.sync.aligned.m16n8k16.row.col.f32.f16.f16.f32 "
                         "{%0,%1,%2,%3}, {%4,%5,%6,%7}, {%8,%9}, {%0,%1,%2,%3};"
                         : "+f"(c1[0]), "+f"(c1[1]), "+f"(c1[2]), "+f"(c1[3])
                         : "r"(a0), "r"(a1), "r"(a2), "r"(a3), "r"(b2), "r"(b3));
        }
    }

    const int row0 = mr * 16 + (lane >> 2);
    const int colb = (lane & 3) * 2;
#pragma unroll
    for (int nb = 0; nb < 8; nb++) {
        int col = nc * 64 + nb * 8 + colb;
        if (base + row0 < N) {
            __half2 h = __floats2half2_rn(acc[nb][0], acc[nb][1]);
            *(unsigned int*)&g_Gh[(size_t)(base + row0) * FD + col] = *(unsigned int*)&h;
        }
        if (base + row0 + 8 < N) {
            __half2 h = __floats2half2_rn(acc[nb][2], acc[nb][3]);
            *(unsigned int*)&g_Gh[(size_t)(base + row0 + 8) * FD + col] = *(unsigned int*)&h;
        }
    }
}

// ---------------------------------------------------------------------------
// 8-half dot with fp32 accumulate.
// ---------------------------------------------------------------------------
__device__ __forceinline__ float dot8(uint4 a, uint4 b) {
    float r = 0.0f;
    {
        float2 x = __half22float2(*(__half2*)&a.x);
        float2 y = __half22float2(*(__half2*)&b.x);
        r += x.x * y.x + x.y * y.y;
    }
    {
        float2 x = __half22float2(*(__half2*)&a.y);
        float2 y = __half22float2(*(__half2*)&b.y);
        r += x.x * y.x + x.y * y.y;
    }
    {
        float2 x = __half22float2(*(__half2*)&a.z);
        float2 y = __half22float2(*(__half2*)&b.z);
        r += x.x * y.x + x.y * y.y;
    }
    {
        float2 x = __half22float2(*(__half2*)&a.w);
        float2 y = __half22float2(*(__half2*)&b.w);
        r += x.x * y.x + x.y * y.y;
    }
    return r;
}

// ---------------------------------------------------------------------------
// Kernel 3: persistent grid-stride edge kernel.
// Half-warp (16 lanes x 16B) per edge row; 8 edges per warp iteration
// (8 LDG.128 of rows in flight = 4KB/warp). Reduction: 3 butterfly levels
// on 4 slot-values + 1 pair-exchange level = 14 shfl / 8 edges.
// slot s, half h -> edge e0 + 2*s + h.
// ---------------------------------------------------------------------------
__global__ __launch_bounds__(256) void edge_kernel(const int* __restrict__ nbr,
                                                   const int* __restrict__ mol,
                                                   float* __restrict__ out, int E) {
    const int warp = threadIdx.x >> 5;
    const int lane = threadIdx.x & 31;
    const int h = lane >> 4;        // half-warp id
    const int t = lane & 15;        // lane within half-warp
    const int nwarps = gridDim.x * 8;
    const int wg = blockIdx.x * 8 + warp;

    const int E8 = E & ~7;

    for (int e0 = wg * 8; e0 < E8; e0 += nwarps * 8) {
        int4 iA = __ldg((const int4*)(nbr + e0));
        int4 iB = __ldg((const int4*)(nbr + e0 + 4));
        int4 jA = __ldg((const int4*)(nbr + (size_t)E + e0));
        int4 jB = __ldg((const int4*)(nbr + (size_t)E + e0 + 4));

        int i0 = h ? iA.y : iA.x;
        int i1 = h ? iA.w : iA.z;
        int i2 = h ? iB.y : iB.x;
        int i3 = h ? iB.w : iB.z;
        int j0 = h ? jA.y : jA.x;
        int j1 = h ? jA.w : jA.z;
        int j2 = h ? jB.y : jB.x;
        int j3 = h ? jB.w : jB.z;

        uint4 ga0 = __ldg((const uint4*)(g_Gh + (size_t)i0 * FD) + t);
        uint4 fb0 = __ldg((const uint4*)(g_Fh + (size_t)j0 * FD) + t);
        uint4 ga1 = __ldg((const uint4*)(g_Gh + (size_t)i1 * FD) + t);
        uint4 fb1 = __ldg((const uint4*)(g_Fh + (size_t)j1 * FD) + t);
        uint4 ga2 = __ldg((const uint4*)(g_Gh + (size_t)i2 * FD) + t);
        uint4 fb2 = __ldg((const uint4*)(g_Fh + (size_t)j2 * FD) + t);
        uint4 ga3 = __ldg((const uint4*)(g_Gh + (size_t)i3 * FD) + t);
        uint4 fb3 = __ldg((const uint4*)(g_Fh + (size_t)j3 * FD) + t);

        float v0 = dot8(ga0, fb0);
        float v1 = dot8(ga1, fb1);
        float v2 = dot8(ga2, fb2);
        float v3 = dot8(ga3, fb3);

        // Butterfly within half-warp over lane bits 3,2,1 -> partial per t-parity.
#pragma unroll
        for (int o = 8; o >= 2; o >>= 1) {
            v0 += __shfl_xor_sync(0xffffffffu, v0, o);
            v1 += __shfl_xor_sync(0xffffffffu, v1, o);
            v2 += __shfl_xor_sync(0xffffffffu, v2, o);
            v3 += __shfl_xor_sync(0xffffffffu, v3, o);
        }
        // Pair-exchange over lane bit 0: lane ends holding full sum of slot (t&1).
        const int p = t & 1;
        float u01 = p ? v1 : v0;
        float w01 = p ? v0 : v1;
        u01 += __shfl_xor_sync(0xffffffffu, w01, 1);
        float u23 = p ? v3 : v2;
        float w23 = p ? v2 : v3;
        u23 += __shfl_xor_sync(0xffffffffu, w23, 1);

        if (t < 2) {
            int4 mA = __ldg((const int4*)(mol + e0));
            int4 mB = __ldg((const int4*)(mol + e0 + 4));
            // edge of u01 = e0 + 2*p + h -> mA component 2p+h; u23 -> mB same.
            int m01 = h ? (p ? mA.w : mA.y) : (p ? mA.z : mA.x);
            int m23 = h ? (p ? mB.w : mB.y) : (p ? mB.z : mB.x);
            atomicAdd(out + m01, u01);
            atomicAdd(out + m23, u23);
        }
    }

    // Tail (E not divisible by 8): warp 0 of block 0, classic 32-lane per edge.
    if (wg == 0) {
        for (int e = E8; e < E; e++) {
            int i = __ldg(&nbr[e]);
            int j = __ldg(&nbr[(size_t)E + e]);
            uint2 ga = __ldg(&((const uint2*)(g_Gh + (size_t)i * FD))[lane]);
            uint2 fb = __ldg(&((const uint2*)(g_Fh + (size_t)j * FD))[lane]);
            float2 a0 = __half22float2(*(__half2*)&ga.x), a1 = __half22float2(*(__half2*)&ga.y);
            float2 b0 = __half22float2(*(__half2*)&fb.x), b1 = __half22float2(*(__half2*)&fb.y);
            float s = a0.x * b0.x + a0.y * b0.y + a1.x * b1.x + a1.y * b1.y;
#pragma unroll
            for (int o = 16; o; o >>= 1) s += __shfl_xor_sync(0xffffffffu, s, o);
            if (lane == 0) atomicAdd(out + __ldg(&mol[e]), s);
        }
    }
}

// ---------------------------------------------------------------------------
// Launch wrapper (graph-capturable: kernel launches only).
// Inputs: [0] feats f32 [N,128], [1] W f32 [128,128],
//         [2] nbr i32 [2,E], [3] mol i32 [E], [4] n_output (use out_size)
// Output: f32 [M]
// ---------------------------------------------------------------------------
extern "C" void kernel_launch(void* const* d_in, const int* in_sizes, int n_in,
                              void* d_out, int out_size) {
    const float* feats = (const float*)d_in[0];
    const float* W = (const float*)d_in[1];
    const int* nbr = (const int*)d_in[2];
    const int* mol = (const int*)d_in[3];
    float* out = (float*)d_out;

    const int N = in_sizes[0] / FD;
    const int E = in_sizes[2] / 2;
    const int M = out_size;

    int prep_elems = FD * FD;
    if (M > prep_elems) prep_elems = M;
    prep_kernel<<<(prep_elems + 255) / 256, 256>>>(W, out, M);

    gemm_mma_kernel<<<(N + 63) / 64, 256>>>(feats, N);

    int blocks = (E + 63) / 64;
    if (blocks > 1184) blocks = 1184;
    if (blocks < 1) blocks = 1;
    edge_kernel<<<blocks, 256>>>(nbr, mol, out, E);
}

// round 8
// speedup vs baseline: 1.0458x; 1.0458x over previous
#include <cuda_runtime.h>
#include <cuda_fp16.h>

#define FD 128
#define NMAX 51200   // headroom over N=50000

// Scratch: Wh = (W + W^T) fp16, G = feats @ Ws (fp16), feats copy (fp16).
__device__ __half g_Wh[FD * FD];
__device__ __half g_Gh[(size_t)NMAX * FD];
__device__ __half g_Fh[(size_t)NMAX * FD];

// ---------------------------------------------------------------------------
// Kernel 1: build Wh = fp16(W + W^T) and zero the (poisoned) output.
// ---------------------------------------------------------------------------
__global__ void prep_kernel(const float* __restrict__ W,
                            float* __restrict__ out, int M) {
    int t = blockIdx.x * blockDim.x + threadIdx.x;
    if (t < FD * FD) {
        int r = t >> 7;
        int c = t & 127;
        g_Wh[t] = __float2half_rn(W[t] + W[c * FD + r]);
    }
    if (t < M) out[t] = 0.0f;
}

// ---------------------------------------------------------------------------
// XOR swizzle on 16-byte chunks.
// ---------------------------------------------------------------------------
__device__ __forceinline__ int swz_off(int row, int col_halves) {
    int chunk = col_halves >> 3;
    int within = col_halves & 7;
    return row * FD + ((chunk ^ (row & 7)) << 3) + within;
}

// ---------------------------------------------------------------------------
// Kernel 2: G = feats @ Ws via HMMA (m16n8k16 fp16 in / fp32 acc).
// Unchanged (measured-good since R6).
// ---------------------------------------------------------------------------
__global__ __launch_bounds__(256) void gemm_mma_kernel(const float* __restrict__ feats,
                                                       int N) {
    __shared__ __half sA[64 * FD];
    __shared__ __half sB[128 * FD];

    const int base = blockIdx.x * 64;
    const int tid = threadIdx.x;

    int nval = N - base;
    if (nval > 64) nval = 64;

    {
        const uint2* src = (const uint2*)g_Wh;
        for (int i = tid; i < 128 * 32; i += 256) {
            int row = i >> 5, c4 = i & 31;
            *(uint2*)&sB[swz_off(row, c4 * 4)] = src[i];
        }
    }
    {
        const float4* src = (const float4*)feats + (size_t)base * 32;
        uint2* fh_dst = (uint2*)(g_Fh + (size_t)base * FD);
        for (int i = tid; i < 64 * 32; i += 256) {
            int row = i >> 5, c4 = i & 31;
            uint2 p = make_uint2(0u, 0u);
            if (row < nval) {
                float4 v = src[i];
                __half2 h0 = __floats2half2_rn(v.x, v.y);
                __half2 h1 = __floats2half2_rn(v.z, v.w);
                p.x = *(unsigned int*)&h0;
                p.y = *(unsigned int*)&h1;
                fh_dst[i] = p;
            }
            *(uint2*)&sA[swz_off(row, c4 * 4)] = p;
        }
    }
    __syncthreads();

    const int warp = tid >> 5;
    const int lane = tid & 31;
    const int mr = warp >> 1;
    const int nc = warp & 1;

    float acc[8][4];
#pragma unroll
    for (int b = 0; b < 8; b++)
#pragma unroll
        for (int q = 0; q < 4; q++) acc[b][q] = 0.0f;

    const int arow = mr * 16 + (lane & 15);
    const int a_kchunk_base = (lane >> 4);
    const int krow_lane = (lane & 7) + ((lane >> 3) & 1) * 8;
    const int b_nadd = (lane >> 4) * 8;

#pragma unroll
    for (int kk = 0; kk < 8; kk++) {
        unsigned a0, a1, a2, a3;
        {
            int koff = kk * 16 + a_kchunk_base * 8;
            unsigned addr = (unsigned)__cvta_generic_to_shared(&sA[swz_off(arow, koff)]);
            asm volatile("ldmatrix.sync.aligned.m8n8.x4.shared.b16 {%0,%1,%2,%3}, [%4];"
                         : "=r"(a0), "=r"(a1), "=r"(a2), "=r"(a3) : "r"(addr));
        }
        const int krow = kk * 16 + krow_lane;
#pragma unroll
        for (int nb2 = 0; nb2 < 4; nb2++) {
            unsigned b0, b1, b2, b3;
            int ncol = nc * 64 + nb2 * 16 + b_nadd;
            unsigned addr = (unsigned)__cvta_generic_to_shared(&sB[swz_off(krow, ncol)]);
            asm volatile("ldmatrix.sync.aligned.m8n8.x4.trans.shared.b16 {%0,%1,%2,%3}, [%4];"
                         : "=r"(b0), "=r"(b1), "=r"(b2), "=r"(b3) : "r"(addr));
            float* c0 = acc[2 * nb2];
            asm volatile("mma.sync.aligned.m16n8k16.row.col.f32.f16.f16.f32 "
                         "{%0,%1,%2,%3}, {%4,%5,%6,%7}, {%8,%9}, {%0,%1,%2,%3};"
                         : "+f"(c0[0]), "+f"(c0[1]), "+f"(c0[2]), "+f"(c0[3])
                         : "r"(a0), "r"(a1), "r"(a2), "r"(a3), "r"(b0), "r"(b1));
            float* c1 = acc[2 * nb2 + 1];
            asm volatile("mma.sync.aligned.m16n8k16.row.col.f32.f16.f16.f32 "
                         "{%0,%1,%2,%3}, {%4,%5,%6,%7}, {%8,%9}, {%0,%1,%2,%3};"
                         : "+f"(c1[0]), "+f"(c1[1]), "+f"(c1[2]), "+f"(c1[3])
                         : "r"(a0), "r"(a1), "r"(a2), "r"(a3), "r"(b2), "r"(b3));
        }
    }

    const int row0 = mr * 16 + (lane >> 2);
    const int colb = (lane & 3) * 2;
#pragma unroll
    for (int nb = 0; nb < 8; nb++) {
        int col = nc * 64 + nb * 8 + colb;
        if (base + row0 < N) {
            __half2 h = __floats2half2_rn(acc[nb][0], acc[nb][1]);
            *(unsigned int*)&g_Gh[(size_t)(base + row0) * FD + col] = *(unsigned int*)&h;
        }
        if (base + row0 + 8 < N) {
            __half2 h = __floats2half2_rn(acc[nb][2], acc[nb][3]);
            *(unsigned int*)&g_Gh[(size_t)(base + row0 + 8) * FD + col] = *(unsigned int*)&h;
        }
    }
}

// ---------------------------------------------------------------------------
// Kernel 3: edge kernel — R6's proven load pattern (4 edges/warp, 8x LDG.64,
// full-warp 256B rows, nL=2/instr) wrapped in a persistent grid-stride loop.
// ---------------------------------------------------------------------------
__global__ __launch_bounds__(256) void edge_kernel(const int* __restrict__ nbr,
                                                   const int* __restrict__ mol,
                                                   float* __restrict__ out, int E) {
    const int warp = threadIdx.x >> 5;
    const int lane = threadIdx.x & 31;
    const int wg = blockIdx.x * 8 + warp;
    const int nwarps = gridDim.x * 8;

    const int E4 = E & ~3;

    for (int e0 = wg * 4; e0 < E4; e0 += nwarps * 4) {
        int4 ii = __ldg((const int4*)(nbr + e0));
        int4 jj = __ldg((const int4*)(nbr + (size_t)E + e0));

        uint2 ga0 = __ldg(&((const uint2*)(g_Gh + (size_t)ii.x * FD))[lane]);
        uint2 ga1 = __ldg(&((const uint2*)(g_Gh + (size_t)ii.y * FD))[lane]);
        uint2 ga2 = __ldg(&((const uint2*)(g_Gh + (size_t)ii.z * FD))[lane]);
        uint2 ga3 = __ldg(&((const uint2*)(g_Gh + (size_t)ii.w * FD))[lane]);
        uint2 fb0 = __ldg(&((const uint2*)(g_Fh + (size_t)jj.x * FD))[lane]);
        uint2 fb1 = __ldg(&((const uint2*)(g_Fh + (size_t)jj.y * FD))[lane]);
        uint2 fb2 = __ldg(&((const uint2*)(g_Fh + (size_t)jj.z * FD))[lane]);
        uint2 fb3 = __ldg(&((const uint2*)(g_Fh + (size_t)jj.w * FD))[lane]);

        float s0, s1, s2, s3;
        {
            float2 a0 = __half22float2(*(__half2*)&ga0.x), a1 = __half22float2(*(__half2*)&ga0.y);
            float2 b0 = __half22float2(*(__half2*)&fb0.x), b1 = __half22float2(*(__half2*)&fb0.y);
            s0 = a0.x * b0.x + a0.y * b0.y + a1.x * b1.x + a1.y * b1.y;
        }
        {
            float2 a0 = __half22float2(*(__half2*)&ga1.x), a1 = __half22float2(*(__half2*)&ga1.y);
            float2 b0 = __half22float2(*(__half2*)&fb1.x), b1 = __half22float2(*(__half2*)&fb1.y);
            s1 = a0.x * b0.x + a0.y * b0.y + a1.x * b1.x + a1.y * b1.y;
        }
        {
            float2 a0 = __half22float2(*(__half2*)&ga2.x), a1 = __half22float2(*(__half2*)&ga2.y);
            float2 b0 = __half22float2(*(__half2*)&fb2.x), b1 = __half22float2(*(__half2*)&fb2.y);
            s2 = a0.x * b0.x + a0.y * b0.y + a1.x * b1.x + a1.y * b1.y;
        }
        {
            float2 a0 = __half22float2(*(__half2*)&ga3.x), a1 = __half22float2(*(__half2*)&ga3.y);
            float2 b0 = __half22float2(*(__half2*)&fb3.x), b1 = __half22float2(*(__half2*)&fb3.y);
            s3 = a0.x * b0.x + a0.y * b0.y + a1.x * b1.x + a1.y * b1.y;
        }

#pragma unroll
        for (int o = 16; o; o >>= 1) {
            s0 += __shfl_xor_sync(0xffffffffu, s0, o);
            s1 += __shfl_xor_sync(0xffffffffu, s1, o);
            s2 += __shfl_xor_sync(0xffffffffu, s2, o);
            s3 += __shfl_xor_sync(0xffffffffu, s3, o);
        }

        if (lane < 4) {
            int4 mm = __ldg((const int4*)(mol + e0));
            float sv = (lane == 0) ? s0 : (lane == 1) ? s1 : (lane == 2) ? s2 : s3;
            int mv = (lane == 0) ? mm.x : (lane == 1) ? mm.y : (lane == 2) ? mm.z : mm.w;
            atomicAdd(out + mv, sv);
        }
    }

    // Tail (E not divisible by 4).
    if (wg == 0) {
        for (int e = E4; e < E; e++) {
            int i = __ldg(&nbr[e]);
            int j = __ldg(&nbr[(size_t)E + e]);
            uint2 ga = __ldg(&((const uint2*)(g_Gh + (size_t)i * FD))[lane]);
            uint2 fb = __ldg(&((const uint2*)(g_Fh + (size_t)j * FD))[lane]);
            float2 a0 = __half22float2(*(__half2*)&ga.x), a1 = __half22float2(*(__half2*)&ga.y);
            float2 b0 = __half22float2(*(__half2*)&fb.x), b1 = __half22float2(*(__half2*)&fb.y);
            float s = a0.x * b0.x + a0.y * b0.y + a1.x * b1.x + a1.y * b1.y;
#pragma unroll
            for (int o = 16; o; o >>= 1) s += __shfl_xor_sync(0xffffffffu, s, o);
            if (lane == 0) atomicAdd(out + __ldg(&mol[e]), s);
        }
    }
}

// ---------------------------------------------------------------------------
// Launch wrapper (graph-capturable: kernel launches only).
// Inputs: [0] feats f32 [N,128], [1] W f32 [128,128],
//         [2] nbr i32 [2,E], [3] mol i32 [E], [4] n_output (use out_size)
// Output: f32 [M]
// ---------------------------------------------------------------------------
extern "C" void kernel_launch(void* const* d_in, const int* in_sizes, int n_in,
                              void* d_out, int out_size) {
    const float* feats = (const float*)d_in[0];
    const float* W = (const float*)d_in[1];
    const int* nbr = (const int*)d_in[2];
    const int* mol = (const int*)d_in[3];
    float* out = (float*)d_out;

    const int N = in_sizes[0] / FD;
    const int E = in_sizes[2] / 2;
    const int M = out_size;

    int prep_elems = FD * FD;
    if (M > prep_elems) prep_elems = M;
    prep_kernel<<<(prep_elems + 255) / 256, 256>>>(W, out, M);

    gemm_mma_kernel<<<(N + 63) / 64, 256>>>(feats, N);

    int blocks = (E + 31) / 32;          // one pass' worth of warps
    if (blocks > 1184) blocks = 1184;    // 8 CTAs/SM persistent
    if (blocks < 1) blocks = 1;
    edge_kernel<<<blocks, 256>>>(nbr, mol, out, E);
}